// round 1
// baseline (speedup 1.0000x reference)
#include <cuda_runtime.h>
#include <cuda_fp16.h>
#include <stdint.h>

#define T_TOK 32768
#define DIM   1024
#define FF    2048
#define NE    8

// ---------------- device scratch (static allocation, allowed) ----------------
__device__ int    g_counts[NE];
__device__ int    g_offsets[NE];
__device__ int    g_is64;
__device__ int    g_tok [NE * T_TOK];
__device__ float  g_gate[NE * T_TOK];
__device__ __half g_xh [(size_t)T_TOK * DIM];            // 64 MB
__device__ __half g_w1h[(size_t)NE * FF * DIM];          // 32 MB
__device__ __half g_w2h[(size_t)NE * DIM * FF];          // 32 MB
__device__ __half g_h  [(size_t)T_TOK * 2 * FF];         // 256 MB (compacted H)

// ---------------- small helpers ----------------
__device__ __forceinline__ void cp16(void* smem, const void* gmem) {
    uint32_t s = (uint32_t)__cvta_generic_to_shared(smem);
    asm volatile("cp.async.cg.shared.global [%0], [%1], 16;\n" :: "r"(s), "l"(gmem));
}
#define CP_COMMIT() asm volatile("cp.async.commit_group;\n" ::: "memory")
#define CP_WAIT(n)  asm volatile("cp.async.wait_group %0;\n" :: "n"(n) : "memory")

__device__ __forceinline__ void mma16816(float* c, const uint32_t* a, uint32_t b0, uint32_t b1) {
    asm volatile(
        "mma.sync.aligned.m16n8k16.row.col.f32.f16.f16.f32 "
        "{%0,%1,%2,%3}, {%4,%5,%6,%7}, {%8,%9}, {%0,%1,%2,%3};\n"
        : "+f"(c[0]), "+f"(c[1]), "+f"(c[2]), "+f"(c[3])
        : "r"(a[0]), "r"(a[1]), "r"(a[2]), "r"(a[3]), "r"(b0), "r"(b1));
}

__device__ __forceinline__ float silu_f(float v) {
    return v * __frcp_rn(1.0f + __expf(-v));
}

// ---------------- prep kernels ----------------
__global__ void zero_out_kernel(float4* out, int n4) {
    int i = blockIdx.x * blockDim.x + threadIdx.x;
    int stride = gridDim.x * blockDim.x;
    float4 z = make_float4(0.f, 0.f, 0.f, 0.f);
    for (int j = i; j < n4; j += stride) out[j] = z;
    if (i < NE) g_counts[i] = 0;
}

__global__ void convert_kernel(const float* __restrict__ src, __half* __restrict__ dst, int n4) {
    int i = blockIdx.x * blockDim.x + threadIdx.x;
    int stride = gridDim.x * blockDim.x;
    for (int j = i; j < n4; j += stride) {
        float4 v = reinterpret_cast<const float4*>(src)[j];
        reinterpret_cast<__half2*>(dst)[2*j]   = __floats2half2_rn(v.x, v.y);
        reinterpret_cast<__half2*>(dst)[2*j+1] = __floats2half2_rn(v.z, v.w);
    }
}

// JAX may silently demote int64 -> int32 (x64 flag). Detect by high-word pattern.
__global__ void detect_kernel(const int* __restrict__ idx_words) {
    if (blockIdx.x == 0 && threadIdx.x == 0) {
        int is64 = 1;
        for (int i = 1; i < 64; i += 2)
            if (idx_words[i] != 0) { is64 = 0; break; }
        g_is64 = is64;
    }
}

__global__ void route_kernel(const void* __restrict__ idx_raw, const float* __restrict__ probs) {
    int t = blockIdx.x * blockDim.x + threadIdx.x;
    if (t >= T_TOK) return;
    int e0, e1;
    if (g_is64) {
        const long long* p = (const long long*)idx_raw;
        e0 = (int)p[2*t]; e1 = (int)p[2*t+1];
    } else {
        const int* p = (const int*)idx_raw;
        e0 = p[2*t]; e1 = p[2*t+1];
    }
    float p0 = probs[2*t], p1 = probs[2*t+1];
    if (e0 == e1) p0 += p1;
    int pos = atomicAdd(&g_counts[e0], 1);
    g_tok [e0 * T_TOK + pos] = t;
    g_gate[e0 * T_TOK + pos] = p0;
    if (e1 != e0) {
        pos = atomicAdd(&g_counts[e1], 1);
        g_tok [e1 * T_TOK + pos] = t;
        g_gate[e1 * T_TOK + pos] = p1;
    }
}

__global__ void scan_kernel() {
    if (threadIdx.x == 0 && blockIdx.x == 0) {
        int s = 0;
        for (int e = 0; e < NE; e++) { g_offsets[e] = s; s += g_counts[e]; }
    }
}

// ---------------- GEMM1: H = silu(X_gather @ W1[e]^T), fp16 out ----------------
// grid: (FF/128, ceil(T/128), NE), 256 threads
__global__ __launch_bounds__(256, 2) void moe_gemm1() {
    const int e = blockIdx.z;
    const int count = g_counts[e];
    const int m0 = blockIdx.y * 128;
    if (m0 >= count) return;
    const int n0 = blockIdx.x * 128;

    __shared__ __half As[2][128 * 40];
    __shared__ __half Bs[2][128 * 40];
    __shared__ int s_tok[128];

    const int tid = threadIdx.x;
    if (tid < 128) {
        int i = m0 + tid;
        s_tok[tid] = g_tok[e * T_TOK + ((i < count) ? i : (count - 1))];
    }
    __syncthreads();

    const int w = tid >> 5, lane = tid & 31;
    const int wm = (w & 3) * 32, wn = (w >> 2) * 64;
    const int g = lane >> 2, t4 = lane & 3;

    float acc[2][8][4];
    #pragma unroll
    for (int i = 0; i < 2; i++)
        #pragma unroll
        for (int j = 0; j < 8; j++)
            #pragma unroll
            for (int q = 0; q < 4; q++) acc[i][j][q] = 0.f;

    const int row_l = tid >> 2;           // 0..63
    const int colh  = (tid & 3) * 8;      // 0,8,16,24 halves

    // prefetch chunk 0
    #pragma unroll
    for (int u = 0; u < 2; u++) {
        int row = row_l + u * 64;
        cp16(&As[0][row * 40 + colh], g_xh  + (size_t)s_tok[row] * DIM + colh);
        cp16(&Bs[0][row * 40 + colh], g_w1h + ((size_t)e * FF + n0 + row) * DIM + colh);
    }
    CP_COMMIT();

    const int KT = DIM / 32;
    for (int kt = 0; kt < KT; kt++) {
        if (kt + 1 < KT) {
            int s = (kt + 1) & 1, k0 = (kt + 1) * 32;
            #pragma unroll
            for (int u = 0; u < 2; u++) {
                int row = row_l + u * 64;
                cp16(&As[s][row * 40 + colh], g_xh  + (size_t)s_tok[row] * DIM + k0 + colh);
                cp16(&Bs[s][row * 40 + colh], g_w1h + ((size_t)e * FF + n0 + row) * DIM + k0 + colh);
            }
            CP_COMMIT();
            CP_WAIT(1);
        } else {
            CP_WAIT(0);
        }
        __syncthreads();
        const int s = kt & 1;
        #pragma unroll
        for (int kk = 0; kk < 2; kk++) {
            const int kb = kk * 16 + t4 * 2;
            uint32_t a[2][4];
            #pragma unroll
            for (int mtl = 0; mtl < 2; mtl++) {
                int r0 = wm + mtl * 16 + g;
                const __half* p0 = &As[s][r0 * 40 + kb];
                const __half* p1 = &As[s][(r0 + 8) * 40 + kb];
                a[mtl][0] = *(const uint32_t*)p0;
                a[mtl][1] = *(const uint32_t*)p1;
                a[mtl][2] = *(const uint32_t*)(p0 + 8);
                a[mtl][3] = *(const uint32_t*)(p1 + 8);
            }
            #pragma unroll
            for (int nt = 0; nt < 8; nt++) {
                int n = wn + nt * 8 + g;
                const __half* pb = &Bs[s][n * 40 + kb];
                uint32_t b0 = *(const uint32_t*)pb;
                uint32_t b1 = *(const uint32_t*)(pb + 8);
                #pragma unroll
                for (int mtl = 0; mtl < 2; mtl++)
                    mma16816(acc[mtl][nt], a[mtl], b0, b1);
            }
        }
        __syncthreads();
    }

    const int hbase = g_offsets[e] + m0;
    #pragma unroll
    for (int mtl = 0; mtl < 2; mtl++) {
        int r0 = wm + mtl * 16 + g;
        int r1 = r0 + 8;
        #pragma unroll
        for (int nt = 0; nt < 8; nt++) {
            int col = n0 + wn + nt * 8 + t4 * 2;
            if (m0 + r0 < count) {
                __half2 h = __floats2half2_rn(silu_f(acc[mtl][nt][0]), silu_f(acc[mtl][nt][1]));
                *(__half2*)&g_h[(size_t)(hbase + r0) * FF + col] = h;
            }
            if (m0 + r1 < count) {
                __half2 h = __floats2half2_rn(silu_f(acc[mtl][nt][2]), silu_f(acc[mtl][nt][3]));
                *(__half2*)&g_h[(size_t)(hbase + r1) * FF + col] = h;
            }
        }
    }
}

// ---------------- GEMM2: out[tok] += gate * (H @ W2[e]^T) ----------------
// grid: (DIM/128, ceil(T/128), NE), 256 threads
__global__ __launch_bounds__(256, 2) void moe_gemm2(float* __restrict__ out) {
    const int e = blockIdx.z;
    const int count = g_counts[e];
    const int m0 = blockIdx.y * 128;
    if (m0 >= count) return;
    const int n0 = blockIdx.x * 128;

    __shared__ __half As[2][128 * 40];
    __shared__ __half Bs[2][128 * 40];
    __shared__ int   s_tok[128];
    __shared__ float s_gate[128];

    const int tid = threadIdx.x;
    const int offs = g_offsets[e];
    if (tid < 128) {
        int i = m0 + tid;
        int ic = (i < count) ? i : (count - 1);
        s_tok [tid] = g_tok [e * T_TOK + ic];
        s_gate[tid] = g_gate[e * T_TOK + ic];
    }
    __syncthreads();

    const int w = tid >> 5, lane = tid & 31;
    const int wm = (w & 3) * 32, wn = (w >> 2) * 64;
    const int g = lane >> 2, t4 = lane & 3;

    float acc[2][8][4];
    #pragma unroll
    for (int i = 0; i < 2; i++)
        #pragma unroll
        for (int j = 0; j < 8; j++)
            #pragma unroll
            for (int q = 0; q < 4; q++) acc[i][j][q] = 0.f;

    const int row_l = tid >> 2;
    const int colh  = (tid & 3) * 8;
    // clamped H row positions for the two rows this thread loads
    int hrow[2];
    #pragma unroll
    for (int u = 0; u < 2; u++) {
        int i = m0 + row_l + u * 64;
        hrow[u] = offs + ((i < count) ? i : (count - 1));
    }

    #pragma unroll
    for (int u = 0; u < 2; u++) {
        int row = row_l + u * 64;
        cp16(&As[0][row * 40 + colh], g_h   + (size_t)hrow[u] * FF + colh);
        cp16(&Bs[0][row * 40 + colh], g_w2h + ((size_t)e * DIM + n0 + row) * FF + colh);
    }
    CP_COMMIT();

    const int KT = FF / 32;
    for (int kt = 0; kt < KT; kt++) {
        if (kt + 1 < KT) {
            int s = (kt + 1) & 1, k0 = (kt + 1) * 32;
            #pragma unroll
            for (int u = 0; u < 2; u++) {
                int row = row_l + u * 64;
                cp16(&As[s][row * 40 + colh], g_h   + (size_t)hrow[u] * FF + k0 + colh);
                cp16(&Bs[s][row * 40 + colh], g_w2h + ((size_t)e * DIM + n0 + row) * FF + k0 + colh);
            }
            CP_COMMIT();
            CP_WAIT(1);
        } else {
            CP_WAIT(0);
        }
        __syncthreads();
        const int s = kt & 1;
        #pragma unroll
        for (int kk = 0; kk < 2; kk++) {
            const int kb = kk * 16 + t4 * 2;
            uint32_t a[2][4];
            #pragma unroll
            for (int mtl = 0; mtl < 2; mtl++) {
                int r0 = wm + mtl * 16 + g;
                const __half* p0 = &As[s][r0 * 40 + kb];
                const __half* p1 = &As[s][(r0 + 8) * 40 + kb];
                a[mtl][0] = *(const uint32_t*)p0;
                a[mtl][1] = *(const uint32_t*)p1;
                a[mtl][2] = *(const uint32_t*)(p0 + 8);
                a[mtl][3] = *(const uint32_t*)(p1 + 8);
            }
            #pragma unroll
            for (int nt = 0; nt < 8; nt++) {
                int n = wn + nt * 8 + g;
                const __half* pb = &Bs[s][n * 40 + kb];
                uint32_t b0 = *(const uint32_t*)pb;
                uint32_t b1 = *(const uint32_t*)(pb + 8);
                #pragma unroll
                for (int mtl = 0; mtl < 2; mtl++)
                    mma16816(acc[mtl][nt], a[mtl], b0, b1);
            }
        }
        __syncthreads();
    }

    #pragma unroll
    for (int mtl = 0; mtl < 2; mtl++) {
        int r0 = wm + mtl * 16 + g;
        int r1 = r0 + 8;
        #pragma unroll
        for (int nt = 0; nt < 8; nt++) {
            int col = n0 + wn + nt * 8 + t4 * 2;
            if (m0 + r0 < count) {
                float gate = s_gate[r0];
                float2 v = make_float2(gate * acc[mtl][nt][0], gate * acc[mtl][nt][1]);
#if __CUDA_ARCH__ >= 900
                atomicAdd(reinterpret_cast<float2*>(&out[(size_t)s_tok[r0] * DIM + col]), v);
#else
                atomicAdd(&out[(size_t)s_tok[r0] * DIM + col],     v.x);
                atomicAdd(&out[(size_t)s_tok[r0] * DIM + col + 1], v.y);
#endif
            }
            if (m0 + r1 < count) {
                float gate = s_gate[r1];
                float2 v = make_float2(gate * acc[mtl][nt][2], gate * acc[mtl][nt][3]);
#if __CUDA_ARCH__ >= 900
                atomicAdd(reinterpret_cast<float2*>(&out[(size_t)s_tok[r1] * DIM + col]), v);
#else
                atomicAdd(&out[(size_t)s_tok[r1] * DIM + col],     v.x);
                atomicAdd(&out[(size_t)s_tok[r1] * DIM + col + 1], v.y);
#endif
            }
        }
    }
}

// ---------------- launcher ----------------
extern "C" void kernel_launch(void* const* d_in, const int* in_sizes, int n_in,
                              void* d_out, int out_size) {
    const float* x     = (const float*)d_in[0];
    const float* probs = (const float*)d_in[1];
    const void*  idx   = d_in[2];
    const float* w1    = (const float*)d_in[3];
    const float* w2    = (const float*)d_in[4];
    float* out = (float*)d_out;

    // resolve device symbol addresses for converts
    __half *p_xh, *p_w1h, *p_w2h;
    cudaGetSymbolAddress((void**)&p_xh,  g_xh);
    cudaGetSymbolAddress((void**)&p_w1h, g_w1h);
    cudaGetSymbolAddress((void**)&p_w2h, g_w2h);

    zero_out_kernel<<<8192, 256>>>((float4*)out, out_size / 4);
    convert_kernel<<<4096, 256>>>(x,  p_xh,  (T_TOK * DIM) / 4);
    convert_kernel<<<4096, 256>>>(w1, p_w1h, (NE * FF * DIM) / 4);
    convert_kernel<<<4096, 256>>>(w2, p_w2h, (NE * DIM * FF) / 4);
    detect_kernel<<<1, 32>>>((const int*)idx);
    route_kernel<<<T_TOK / 256, 256>>>(idx, probs);
    scan_kernel<<<1, 32>>>();

    dim3 g1(FF / 128, T_TOK / 128, NE);
    moe_gemm1<<<g1, 256>>>();
    dim3 g2(DIM / 128, T_TOK / 128, NE);
    moe_gemm2<<<g2, 256>>>(out);
}